// round 16
// baseline (speedup 1.0000x reference)
#include <cuda_runtime.h>
#include <cuda_fp16.h>
#include <math.h>

#define T_TOK 8192
#define D_DIM 1024
#define H_DIM 2048
#define NE    8
#define CH    64
#define STAGES 3
#define STG_BYTES 32768
#define SMEM_BYTES (2048 + STAGES * STG_BYTES)

typedef unsigned int u32;
typedef unsigned long long u64;

// ---------------- static device scratch ----------------
__device__ int    g_cnt[NE];
__device__ float  g_imp[NE];
__device__ int    g_btok[NE * T_TOK];
__device__ int2   g_slot[T_TOK];
__device__ float2 g_tw[T_TOK];
__device__ __half g_x16[(size_t)T_TOK * D_DIM];
__device__ __half g_w1[(size_t)NE * H_DIM * D_DIM];    // W1^T fp16 [e][h][d]
__device__ __half g_w2[(size_t)NE * D_DIM * H_DIM];    // W2^T fp16 [e][d][h]
__device__ __half g_h[(size_t)NE * T_TOK * H_DIM];     // hidden fp16
__device__ __half g_y[(size_t)NE * T_TOK * D_DIM];     // expert outputs (y + b2), fp16

// ---------------- helpers ----------------
__device__ __forceinline__ u32 cvta_smem(const void* p) {
    u32 a;
    asm("{ .reg .u64 t; cvta.to.shared.u64 t, %1; cvt.u32.u64 %0, t; }" : "=r"(a) : "l"(p));
    return a;
}
__device__ __forceinline__ void cp16(u32 dst, const void* src) {
    asm volatile("cp.async.cg.shared.global [%0], [%1], 16;" :: "r"(dst), "l"(src));
}
__device__ __forceinline__ void cp_commit() { asm volatile("cp.async.commit_group;"); }
__device__ __forceinline__ void ldsm4(u32& r0, u32& r1, u32& r2, u32& r3, u32 addr) {
    asm volatile("ldmatrix.sync.aligned.m8n8.x4.shared.b16 {%0,%1,%2,%3}, [%4];"
                 : "=r"(r0), "=r"(r1), "=r"(r2), "=r"(r3) : "r"(addr));
}
__device__ __forceinline__ void mma_f32(float* c, const u32* a, u32 b0, u32 b1) {
    asm volatile("mma.sync.aligned.m16n8k16.row.col.f32.f16.f16.f32 "
                 "{%0,%1,%2,%3}, {%4,%5,%6,%7}, {%8,%9}, {%0,%1,%2,%3};"
                 : "+f"(c[0]), "+f"(c[1]), "+f"(c[2]), "+f"(c[3])
                 : "r"(a[0]), "r"(a[1]), "r"(a[2]), "r"(a[3]), "r"(b0), "r"(b1));
}
__device__ __forceinline__ u32 swz128(u32 o) { return o ^ ((o >> 3) & 0x70); }
__device__ __forceinline__ u32 pack_h2(__half a, __half b) {
    unsigned short ua = *reinterpret_cast<unsigned short*>(&a);
    unsigned short ub = *reinterpret_cast<unsigned short*>(&b);
    return (u32)ua | ((u32)ub << 16);
}
// fast GELU: tanh form with HW tanh.approx (sm_75+)
__device__ __forceinline__ float gelu_fast(float v) {
    float u = 0.7978845608028654f * v * (1.f + 0.044715f * v * v);
    float t;
    asm("tanh.approx.f32 %0, %1;" : "=f"(t) : "f"(u));
    return 0.5f * v * (1.f + t);
}

// ---------------------------------------------------------------------------
// both weight transposes in one launch; block 0 also zeroes the counters
// (this kernel launches FIRST, so stream ordering protects the router)
// ---------------------------------------------------------------------------
__global__ __launch_bounds__(256) void convT2_kernel(const float* __restrict__ W1,
                                                     const float* __restrict__ W2)
{
    if (blockIdx.x == 0 && threadIdx.x < NE) {
        g_cnt[threadIdx.x] = 0;
        g_imp[threadIdx.x] = 0.f;
    }
    __shared__ float s[32][33];
    int tx = threadIdx.x & 31, ty = threadIdx.x >> 5;
    int gid = blockIdx.x;
    const float* ip;
    __half* op;
    int R, C, c0, r0, e;
    if (gid < 16384) {
        e = gid >> 11;
        int rem = gid & 2047;
        c0 = (rem & 63) * 32; r0 = (rem >> 6) * 32;
        R = D_DIM; C = H_DIM;
        ip = W1 + (size_t)e * R * C;
        op = g_w1;
    } else {
        gid -= 16384;
        e = gid >> 11;
        int rem = gid & 2047;
        c0 = (rem & 31) * 32; r0 = (rem >> 5) * 32;
        R = H_DIM; C = D_DIM;
        ip = W2 + (size_t)e * R * C;
        op = g_w2;
    }
#pragma unroll
    for (int k = 0; k < 32; k += 8)
        s[ty + k][tx] = ip[(size_t)(r0 + ty + k) * C + c0 + tx];
    __syncthreads();
#pragma unroll
    for (int k = 0; k < 32; k += 8) {
        float v = s[tx][ty + k];
        size_t oo = ((size_t)e * C + c0 + ty + k) * R + r0 + tx;
        op[oo] = __float2half_rn(v);
    }
}

// ---------------------------------------------------------------------------
// router: one warp per token (float4 loads); also writes x -> fp16
// ---------------------------------------------------------------------------
__global__ __launch_bounds__(256) void router_kernel(
    const float* __restrict__ x,
    const float* __restrict__ Wr,
    const float* __restrict__ br)
{
    __shared__ float sWr[D_DIM * NE];
    __shared__ float s_imp[NE];
    int tid = threadIdx.x;
    for (int i = tid; i < D_DIM * NE; i += 256) sWr[i] = Wr[i];
    if (tid < NE) s_imp[tid] = 0.f;
    __syncthreads();

    int warp = tid >> 5, lane = tid & 31;
    int t = blockIdx.x * 8 + warp;

    float acc[NE];
#pragma unroll
    for (int e = 0; e < NE; e++) acc[e] = 0.f;

    const float4* xr = reinterpret_cast<const float4*>(x + (size_t)t * D_DIM);
    uint2* xo = reinterpret_cast<uint2*>(g_x16 + (size_t)t * D_DIM);
#pragma unroll
    for (int i = 0; i < 8; i++) {
        int q = lane + 32 * i;          // float4 index within row (0..255)
        float4 v = xr[q];
        // fp16 conversion store (replaces the old prep pass)
        xo[q] = make_uint2(pack_h2(__float2half_rn(v.x), __float2half_rn(v.y)),
                           pack_h2(__float2half_rn(v.z), __float2half_rn(v.w)));
        int d = q * 4;
#pragma unroll
        for (int e = 0; e < NE; e++) {
            acc[e] += v.x * sWr[(d + 0) * NE + e]
                    + v.y * sWr[(d + 1) * NE + e]
                    + v.z * sWr[(d + 2) * NE + e]
                    + v.w * sWr[(d + 3) * NE + e];
        }
    }
#pragma unroll
    for (int e = 0; e < NE; e++) {
#pragma unroll
        for (int off = 16; off > 0; off >>= 1)
            acc[e] += __shfl_down_sync(0xffffffffu, acc[e], off);
    }

    if (lane == 0) {
        float p[NE];
        float mx = -1e30f;
#pragma unroll
        for (int e = 0; e < NE; e++) { p[e] = acc[e] + br[e]; mx = fmaxf(mx, p[e]); }
        float s = 0.f;
#pragma unroll
        for (int e = 0; e < NE; e++) { p[e] = expf(p[e] - mx); s += p[e]; }
        float inv = 1.f / s;
#pragma unroll
        for (int e = 0; e < NE; e++) {
            p[e] *= inv;
            atomicAdd(&s_imp[e], p[e]);
        }
        int i0 = 0;
#pragma unroll
        for (int e = 1; e < NE; e++) if (p[e] > p[i0]) i0 = e;
        int i1 = -1;
        float best1 = -1.f;
#pragma unroll
        for (int e = 0; e < NE; e++) {
            if (e == i0) continue;
            if (p[e] > best1) { best1 = p[e]; i1 = e; }
        }
        float w0 = p[i0], w1 = p[i1];
        float ws = fmaxf(w0 + w1, 1e-9f);
        w0 /= ws; w1 /= ws;

        int s0 = atomicAdd(&g_cnt[i0], 1);
        g_btok[i0 * T_TOK + s0] = t;
        int s1 = atomicAdd(&g_cnt[i1], 1);
        g_btok[i1 * T_TOK + s1] = t;
        g_slot[t] = make_int2(i0 * T_TOK + s0, i1 * T_TOK + s1);
        g_tw[t]   = make_float2(w0, w1);
    }
    __syncthreads();
    if (tid < NE) atomicAdd(&g_imp[tid], s_imp[tid]);
}

// ---------------------------------------------------------------------------
// GEMM core: 128 threads (4 warps), tile 128x128, warptile 64x64
// ---------------------------------------------------------------------------
__device__ __forceinline__ void gemm_inner(float acc[4][8][4], u32 base,
                                           int wm, int wn, int lane) {
    int klo = (lane >> 4) * 16;
    u32 aAddr[4], aMask[4], bAddr[4], bMask[4];
#pragma unroll
    for (int mf = 0; mf < 4; ++mf) {
        int rr = wm * 64 + mf * 16 + (lane & 15);
        aAddr[mf] = base + (rr << 7);
        aMask[mf] = (rr & 7) << 4;
    }
#pragma unroll
    for (int g = 0; g < 4; ++g) {
        int rr = wn * 64 + g * 16 + (lane & 15);
        bAddr[g] = base + 16384 + (rr << 7);
        bMask[g] = (rr & 7) << 4;
    }
#pragma unroll
    for (int ks = 0; ks < 4; ++ks) {
        u32 a[4][4], b[4][4];
        u32 kk = ks * 32 + klo;
#pragma unroll
        for (int mf = 0; mf < 4; ++mf)
            ldsm4(a[mf][0], a[mf][1], a[mf][2], a[mf][3],
                  aAddr[mf] + (kk ^ aMask[mf]));
#pragma unroll
        for (int g = 0; g < 4; ++g)
            ldsm4(b[g][0], b[g][1], b[g][2], b[g][3],
                  bAddr[g] + (kk ^ bMask[g]));
#pragma unroll
        for (int mf = 0; mf < 4; ++mf)
#pragma unroll
            for (int nf = 0; nf < 8; ++nf) {
                int g = nf >> 1, h = nf & 1;
                mma_f32(acc[mf][nf], a[mf], b[g][h], b[g][2 + h]);
            }
    }
}

// ---------------------------------------------------------------------------
// GEMM1: x16 @ W1 -> gelu -> g_h   (tile 128x128, 128 threads, 2 CTAs/SM)
// ---------------------------------------------------------------------------
__global__ __launch_bounds__(128, 2) void gemm1_mma(const float* __restrict__ b1)
{
    int e    = blockIdx.z;
    int cnt  = g_cnt[e];
    int row0 = blockIdx.y * 128;
    if (row0 >= cnt) return;
    int n0 = blockIdx.x * 128;

    extern __shared__ char smem[];
    float* sBias = (float*)smem;
    int*   stok  = (int*)(smem + 1024);
    u32 tb = cvta_smem(smem + 2048);

    int tid = threadIdx.x, lane = tid & 31, wid = tid >> 5;
    int wm = wid & 1, wn = wid >> 1;

    sBias[tid] = b1[e * H_DIM + n0 + tid];
    {
        int r = row0 + tid;
        stok[tid] = (r < cnt) ? g_btok[e * T_TOK + r] : 0;
    }
    __syncthreads();

    const __half* Bp = g_w1 + ((size_t)e * H_DIM + n0) * D_DIM;

    int rbase = tid >> 3, cq = tid & 7;
    u32 dOff[8];
    const __half* aSrc[8];
    const __half* bSrc[8];
#pragma unroll
    for (int t = 0; t < 8; t++) {
        int row = t * 16 + rbase;
        dOff[t] = swz128((row << 7) + (cq << 4));
        aSrc[t] = g_x16 + (size_t)stok[row] * D_DIM + cq * 8;
        bSrc[t] = Bp + (size_t)row * D_DIM + cq * 8;
    }

    const int NCH = D_DIM / CH;   // 16
    auto issue = [&](int it, int s) {
        int k0 = it * CH;
        u32 base = tb + s * STG_BYTES;
#pragma unroll
        for (int t = 0; t < 8; t++)
            cp16(base + dOff[t], aSrc[t] + k0);
#pragma unroll
        for (int t = 0; t < 8; t++)
            cp16(base + 16384 + dOff[t], bSrc[t] + k0);
        cp_commit();
    };
    issue(0, 0); issue(1, 1);

    float acc[4][8][4];
#pragma unroll
    for (int i = 0; i < 4; i++)
#pragma unroll
        for (int j = 0; j < 8; j++)
#pragma unroll
            for (int k = 0; k < 4; k++) acc[i][j][k] = 0.f;

    for (int it = 0; it < NCH; ++it) {
        asm volatile("cp.async.wait_group 1;" ::: "memory");
        __syncthreads();
        if (it + 2 < NCH) issue(it + 2, (it + 2) % STAGES);
        gemm_inner(acc, tb + (it % STAGES) * STG_BYTES, wm, wn, lane);
    }

    // epilogue: bias + fast gelu -> fp16
#pragma unroll
    for (int mf = 0; mf < 4; ++mf) {
        int rb = row0 + wm * 64 + mf * 16 + (lane >> 2);
#pragma unroll
        for (int half = 0; half < 2; ++half) {
            int r = rb + half * 8;
            if (r < cnt) {
                size_t rowoff = ((size_t)e * T_TOK + r) * H_DIM;
#pragma unroll
                for (int nf = 0; nf < 8; ++nf) {
                    int cl = wn * 64 + nf * 8 + (lane & 3) * 2;
                    float v0 = gelu_fast(acc[mf][nf][half * 2 + 0] + sBias[cl]);
                    float v1 = gelu_fast(acc[mf][nf][half * 2 + 1] + sBias[cl + 1]);
                    *reinterpret_cast<u32*>(g_h + rowoff + n0 + cl) =
                        pack_h2(__float2half_rn(v0), __float2half_rn(v1));
                }
            }
        }
    }
}

// ---------------------------------------------------------------------------
// GEMM2: h @ W2 -> g_y (fp16, plain stores)
// ---------------------------------------------------------------------------
__global__ __launch_bounds__(128, 2) void gemm2_mma(const float* __restrict__ b2)
{
    int e    = blockIdx.z;
    int cnt  = g_cnt[e];
    int row0 = blockIdx.y * 128;
    if (row0 >= cnt) return;
    int n0 = blockIdx.x * 128;

    extern __shared__ char smem[];
    float* sBias = (float*)smem;
    u32 tb = cvta_smem(smem + 2048);

    int tid = threadIdx.x, lane = tid & 31, wid = tid >> 5;
    int wm = wid & 1, wn = wid >> 1;

    sBias[tid] = b2[e * D_DIM + n0 + tid];
    __syncthreads();

    const __half* Ap = g_h + (size_t)e * T_TOK * H_DIM;
    const __half* Bp = g_w2 + ((size_t)e * D_DIM + n0) * H_DIM;

    int rbase = tid >> 3, cq = tid & 7;
    u32 dOff[8];
    const __half* aSrc[8];
    const __half* bSrc[8];
#pragma unroll
    for (int t = 0; t < 8; t++) {
        int row = t * 16 + rbase;
        dOff[t] = swz128((row << 7) + (cq << 4));
        int rr = row0 + row;
        if (rr >= cnt) rr = cnt - 1;
        aSrc[t] = Ap + (size_t)rr * H_DIM + cq * 8;
        bSrc[t] = Bp + (size_t)row * H_DIM + cq * 8;
    }

    const int NCH = H_DIM / CH;   // 32
    auto issue = [&](int it, int s) {
        int k0 = it * CH;
        u32 base = tb + s * STG_BYTES;
#pragma unroll
        for (int t = 0; t < 8; t++)
            cp16(base + dOff[t], aSrc[t] + k0);
#pragma unroll
        for (int t = 0; t < 8; t++)
            cp16(base + 16384 + dOff[t], bSrc[t] + k0);
        cp_commit();
    };
    issue(0, 0); issue(1, 1);

    float acc[4][8][4];
#pragma unroll
    for (int i = 0; i < 4; i++)
#pragma unroll
        for (int j = 0; j < 8; j++)
#pragma unroll
            for (int k = 0; k < 4; k++) acc[i][j][k] = 0.f;

    for (int it = 0; it < NCH; ++it) {
        asm volatile("cp.async.wait_group 1;" ::: "memory");
        __syncthreads();
        if (it + 2 < NCH) issue(it + 2, (it + 2) % STAGES);
        gemm_inner(acc, tb + (it % STAGES) * STG_BYTES, wm, wn, lane);
    }

    // epilogue: g_y = fp16(y + b2)
#pragma unroll
    for (int mf = 0; mf < 4; ++mf) {
        int rb = row0 + wm * 64 + mf * 16 + (lane >> 2);
#pragma unroll
        for (int half = 0; half < 2; ++half) {
            int r = rb + half * 8;
            if (r < cnt) {
                __half* yrow = g_y + ((size_t)e * T_TOK + r) * D_DIM + n0;
#pragma unroll
                for (int nf = 0; nf < 8; ++nf) {
                    int cl = wn * 64 + nf * 8 + (lane & 3) * 2;
                    float v0 = acc[mf][nf][half * 2 + 0] + sBias[cl];
                    float v1 = acc[mf][nf][half * 2 + 1] + sBias[cl + 1];
                    *reinterpret_cast<u32*>(yrow + cl) =
                        pack_h2(__float2half_rn(v0), __float2half_rn(v1));
                }
            }
        }
    }
}

// ---------------------------------------------------------------------------
// combine: out[t] = w0*y[slot0] + w1*y[slot1] (fp16 sources); + aux loss
// ---------------------------------------------------------------------------
__global__ __launch_bounds__(512) void combine_kernel(float* __restrict__ out,
                                                      int do_aux)
{
    size_t i = (size_t)blockIdx.x * blockDim.x + threadIdx.x;   // T*D/4
    int t = (int)(i >> 8);
    int d4 = (int)(i & 255);
    int2   sl = g_slot[t];
    float2 w  = g_tw[t];
    uint2 p0 = reinterpret_cast<const uint2*>(g_y)[(size_t)sl.x * 256 + d4];
    uint2 p1 = reinterpret_cast<const uint2*>(g_y)[(size_t)sl.y * 256 + d4];
    float2 a0 = __half22float2(*reinterpret_cast<__half2*>(&p0.x));
    float2 a1 = __half22float2(*reinterpret_cast<__half2*>(&p0.y));
    float2 b0 = __half22float2(*reinterpret_cast<__half2*>(&p1.x));
    float2 b1 = __half22float2(*reinterpret_cast<__half2*>(&p1.y));
    float4 o;
    o.x = w.x * a0.x + w.y * b0.x;
    o.y = w.x * a0.y + w.y * b0.y;
    o.z = w.x * a1.x + w.y * b1.x;
    o.w = w.x * a1.y + w.y * b1.y;
    reinterpret_cast<float4*>(out)[i] = o;

    if (do_aux && blockIdx.x == 0 && threadIdx.x == 0) {
        int tot = 0;
#pragma unroll
        for (int e = 0; e < NE; e++) tot += g_cnt[e];
        float denom = fmaxf((float)tot, 1.f);
        float s = 0.f;
#pragma unroll
        for (int e = 0; e < NE; e++)
            s += (g_imp[e] / (float)T_TOK) * ((float)g_cnt[e] / denom);
        out[(size_t)T_TOK * D_DIM] = (float)NE * s;
    }
}

// ---------------------------------------------------------------------------
extern "C" void kernel_launch(void* const* d_in, const int* in_sizes, int n_in,
                              void* d_out, int out_size)
{
    const float* x  = (const float*)d_in[0];
    const float* Wr = (const float*)d_in[1];
    const float* br = (const float*)d_in[2];
    const float* W1 = (const float*)d_in[3];
    const float* b1 = (const float*)d_in[4];
    const float* W2 = (const float*)d_in[5];
    const float* b2 = (const float*)d_in[6];
    float* out = (float*)d_out;

    cudaFuncSetAttribute(gemm1_mma, cudaFuncAttributeMaxDynamicSharedMemorySize, SMEM_BYTES);
    cudaFuncSetAttribute(gemm2_mma, cudaFuncAttributeMaxDynamicSharedMemorySize, SMEM_BYTES);

    int do_aux = (out_size > T_TOK * D_DIM) ? 1 : 0;

    convT2_kernel<<<32768, 256>>>(W1, W2);
    router_kernel<<<T_TOK / 8, 256>>>(x, Wr, br);
    gemm1_mma<<<dim3(H_DIM / 128, T_TOK / 128, NE), 128, SMEM_BYTES>>>(b1);
    gemm2_mma<<<dim3(D_DIM / 128, T_TOK / 128, NE), 128, SMEM_BYTES>>>(b2);
    combine_kernel<<<T_TOK * D_DIM / 4 / 512, 512>>>(out, do_aux);
}

// round 17
// speedup vs baseline: 1.0840x; 1.0840x over previous
#include <cuda_runtime.h>
#include <cuda_fp16.h>
#include <math.h>

#define T_TOK 8192
#define D_DIM 1024
#define H_DIM 2048
#define NE    8
#define CH    64
#define STAGES 3
#define STG_BYTES 32768
#define SMEM_BYTES (2048 + STAGES * STG_BYTES)

typedef unsigned int u32;
typedef unsigned long long u64;

// ---------------- static device scratch ----------------
__device__ int    g_cnt[NE];
__device__ float  g_imp[NE];
__device__ int    g_btok[NE * T_TOK];
__device__ int2   g_slot[T_TOK];
__device__ float2 g_tw[T_TOK];
__device__ __half g_x16[(size_t)T_TOK * D_DIM];
__device__ __half g_w1[(size_t)NE * H_DIM * D_DIM];    // W1^T fp16 [e][h][d]
__device__ __half g_w2[(size_t)NE * D_DIM * H_DIM];    // W2^T fp16 [e][d][h]
__device__ __half g_h[(size_t)NE * T_TOK * H_DIM];     // hidden fp16
__device__ __half g_y[(size_t)NE * T_TOK * D_DIM];     // expert outputs (y + b2), fp16

// ---------------- helpers ----------------
__device__ __forceinline__ u32 cvta_smem(const void* p) {
    u32 a;
    asm("{ .reg .u64 t; cvta.to.shared.u64 t, %1; cvt.u32.u64 %0, t; }" : "=r"(a) : "l"(p));
    return a;
}
__device__ __forceinline__ void cp16(u32 dst, const void* src) {
    asm volatile("cp.async.cg.shared.global [%0], [%1], 16;" :: "r"(dst), "l"(src));
}
__device__ __forceinline__ void cp_commit() { asm volatile("cp.async.commit_group;"); }
__device__ __forceinline__ void ldsm4(u32& r0, u32& r1, u32& r2, u32& r3, u32 addr) {
    asm volatile("ldmatrix.sync.aligned.m8n8.x4.shared.b16 {%0,%1,%2,%3}, [%4];"
                 : "=r"(r0), "=r"(r1), "=r"(r2), "=r"(r3) : "r"(addr));
}
__device__ __forceinline__ void mma_f32(float* c, const u32* a, u32 b0, u32 b1) {
    asm volatile("mma.sync.aligned.m16n8k16.row.col.f32.f16.f16.f32 "
                 "{%0,%1,%2,%3}, {%4,%5,%6,%7}, {%8,%9}, {%0,%1,%2,%3};"
                 : "+f"(c[0]), "+f"(c[1]), "+f"(c[2]), "+f"(c[3])
                 : "r"(a[0]), "r"(a[1]), "r"(a[2]), "r"(a[3]), "r"(b0), "r"(b1));
}
__device__ __forceinline__ u32 swz128(u32 o) { return o ^ ((o >> 3) & 0x70); }
__device__ __forceinline__ u32 pack_h2(__half a, __half b) {
    unsigned short ua = *reinterpret_cast<unsigned short*>(&a);
    unsigned short ub = *reinterpret_cast<unsigned short*>(&b);
    return (u32)ua | ((u32)ub << 16);
}
// fast GELU: tanh form with HW tanh.approx (sm_75+)
__device__ __forceinline__ float gelu_fast(float v) {
    float u = 0.7978845608028654f * v * (1.f + 0.044715f * v * v);
    float t;
    asm("tanh.approx.f32 %0, %1;" : "=f"(t) : "f"(u));
    return 0.5f * v * (1.f + t);
}

// ---------------------------------------------------------------------------
// prep: convert x -> fp16 + reset counters
// ---------------------------------------------------------------------------
__global__ __launch_bounds__(512) void prep_kernel(const float* __restrict__ x) {
    size_t i = (size_t)blockIdx.x * blockDim.x + threadIdx.x;
    float4 v = reinterpret_cast<const float4*>(x)[i];
    reinterpret_cast<uint2*>(g_x16)[i] =
        make_uint2(pack_h2(__float2half_rn(v.x), __float2half_rn(v.y)),
                   pack_h2(__float2half_rn(v.z), __float2half_rn(v.w)));
    if (blockIdx.x == 0 && threadIdx.x < NE) {
        g_cnt[threadIdx.x] = 0;
        g_imp[threadIdx.x] = 0.f;
    }
}

// ---------------------------------------------------------------------------
// router: one warp per token (scalar smem reads, stride-8, conflict-benign)
// ---------------------------------------------------------------------------
__global__ __launch_bounds__(256) void router_kernel(
    const float* __restrict__ x,
    const float* __restrict__ Wr,
    const float* __restrict__ br)
{
    __shared__ float sWr[D_DIM * NE];
    __shared__ float s_imp[NE];
    int tid = threadIdx.x;
    for (int i = tid; i < D_DIM * NE; i += 256) sWr[i] = Wr[i];
    if (tid < NE) s_imp[tid] = 0.f;
    __syncthreads();

    int warp = tid >> 5, lane = tid & 31;
    int t = blockIdx.x * 8 + warp;

    float acc[NE];
#pragma unroll
    for (int e = 0; e < NE; e++) acc[e] = 0.f;

    const float* xr = x + (size_t)t * D_DIM;
    for (int d = lane; d < D_DIM; d += 32) {
        float xv = xr[d];
#pragma unroll
        for (int e = 0; e < NE; e++) acc[e] += xv * sWr[d * NE + e];
    }
#pragma unroll
    for (int e = 0; e < NE; e++) {
#pragma unroll
        for (int off = 16; off > 0; off >>= 1)
            acc[e] += __shfl_down_sync(0xffffffffu, acc[e], off);
    }

    if (lane == 0) {
        float p[NE];
        float mx = -1e30f;
#pragma unroll
        for (int e = 0; e < NE; e++) { p[e] = acc[e] + br[e]; mx = fmaxf(mx, p[e]); }
        float s = 0.f;
#pragma unroll
        for (int e = 0; e < NE; e++) { p[e] = expf(p[e] - mx); s += p[e]; }
        float inv = 1.f / s;
#pragma unroll
        for (int e = 0; e < NE; e++) {
            p[e] *= inv;
            atomicAdd(&s_imp[e], p[e]);
        }
        int i0 = 0;
#pragma unroll
        for (int e = 1; e < NE; e++) if (p[e] > p[i0]) i0 = e;
        int i1 = -1;
        float best1 = -1.f;
#pragma unroll
        for (int e = 0; e < NE; e++) {
            if (e == i0) continue;
            if (p[e] > best1) { best1 = p[e]; i1 = e; }
        }
        float w0 = p[i0], w1 = p[i1];
        float ws = fmaxf(w0 + w1, 1e-9f);
        w0 /= ws; w1 /= ws;

        int s0 = atomicAdd(&g_cnt[i0], 1);
        g_btok[i0 * T_TOK + s0] = t;
        int s1 = atomicAdd(&g_cnt[i1], 1);
        g_btok[i1 * T_TOK + s1] = t;
        g_slot[t] = make_int2(i0 * T_TOK + s0, i1 * T_TOK + s1);
        g_tw[t]   = make_float2(w0, w1);
    }
    __syncthreads();
    if (tid < NE) atomicAdd(&g_imp[tid], s_imp[tid]);
}

// ---------------------------------------------------------------------------
// both weight transposes in one launch
// ---------------------------------------------------------------------------
__global__ __launch_bounds__(256) void convT2_kernel(const float* __restrict__ W1,
                                                     const float* __restrict__ W2)
{
    __shared__ float s[32][33];
    int tx = threadIdx.x & 31, ty = threadIdx.x >> 5;
    int gid = blockIdx.x;
    const float* ip;
    __half* op;
    int R, C, c0, r0, e;
    if (gid < 16384) {
        e = gid >> 11;
        int rem = gid & 2047;
        c0 = (rem & 63) * 32; r0 = (rem >> 6) * 32;
        R = D_DIM; C = H_DIM;
        ip = W1 + (size_t)e * R * C;
        op = g_w1;
    } else {
        gid -= 16384;
        e = gid >> 11;
        int rem = gid & 2047;
        c0 = (rem & 31) * 32; r0 = (rem >> 5) * 32;
        R = H_DIM; C = D_DIM;
        ip = W2 + (size_t)e * R * C;
        op = g_w2;
    }
#pragma unroll
    for (int k = 0; k < 32; k += 8)
        s[ty + k][tx] = ip[(size_t)(r0 + ty + k) * C + c0 + tx];
    __syncthreads();
#pragma unroll
    for (int k = 0; k < 32; k += 8) {
        float v = s[tx][ty + k];
        size_t oo = ((size_t)e * C + c0 + ty + k) * R + r0 + tx;
        op[oo] = __float2half_rn(v);
    }
}

// ---------------------------------------------------------------------------
// GEMM core: 128 threads (4 warps), tile 128x128, warptile 64x64
// ---------------------------------------------------------------------------
__device__ __forceinline__ void gemm_inner(float acc[4][8][4], u32 base,
                                           int wm, int wn, int lane) {
    int klo = (lane >> 4) * 16;
    u32 aAddr[4], aMask[4], bAddr[4], bMask[4];
#pragma unroll
    for (int mf = 0; mf < 4; ++mf) {
        int rr = wm * 64 + mf * 16 + (lane & 15);
        aAddr[mf] = base + (rr << 7);
        aMask[mf] = (rr & 7) << 4;
    }
#pragma unroll
    for (int g = 0; g < 4; ++g) {
        int rr = wn * 64 + g * 16 + (lane & 15);
        bAddr[g] = base + 16384 + (rr << 7);
        bMask[g] = (rr & 7) << 4;
    }
#pragma unroll
    for (int ks = 0; ks < 4; ++ks) {
        u32 a[4][4], b[4][4];
        u32 kk = ks * 32 + klo;
#pragma unroll
        for (int mf = 0; mf < 4; ++mf)
            ldsm4(a[mf][0], a[mf][1], a[mf][2], a[mf][3],
                  aAddr[mf] + (kk ^ aMask[mf]));
#pragma unroll
        for (int g = 0; g < 4; ++g)
            ldsm4(b[g][0], b[g][1], b[g][2], b[g][3],
                  bAddr[g] + (kk ^ bMask[g]));
#pragma unroll
        for (int mf = 0; mf < 4; ++mf)
#pragma unroll
            for (int nf = 0; nf < 8; ++nf) {
                int g = nf >> 1, h = nf & 1;
                mma_f32(acc[mf][nf], a[mf], b[g][h], b[g][2 + h]);
            }
    }
}

// ---------------------------------------------------------------------------
// GEMM1: x16 @ W1 -> gelu -> g_h   (tile 128x128, 128 threads, 2 CTAs/SM)
// ---------------------------------------------------------------------------
__global__ __launch_bounds__(128, 2) void gemm1_mma(const float* __restrict__ b1)
{
    int e    = blockIdx.z;
    int cnt  = g_cnt[e];
    int row0 = blockIdx.y * 128;
    if (row0 >= cnt) return;
    int n0 = blockIdx.x * 128;

    extern __shared__ char smem[];
    float* sBias = (float*)smem;
    int*   stok  = (int*)(smem + 1024);
    u32 tb = cvta_smem(smem + 2048);

    int tid = threadIdx.x, lane = tid & 31, wid = tid >> 5;
    int wm = wid & 1, wn = wid >> 1;

    sBias[tid] = b1[e * H_DIM + n0 + tid];
    {
        int r = row0 + tid;
        stok[tid] = (r < cnt) ? g_btok[e * T_TOK + r] : 0;
    }
    __syncthreads();

    const __half* Bp = g_w1 + ((size_t)e * H_DIM + n0) * D_DIM;

    int rbase = tid >> 3, cq = tid & 7;
    u32 dOff[8];
    const __half* aSrc[8];
    const __half* bSrc[8];
#pragma unroll
    for (int t = 0; t < 8; t++) {
        int row = t * 16 + rbase;
        dOff[t] = swz128((row << 7) + (cq << 4));
        aSrc[t] = g_x16 + (size_t)stok[row] * D_DIM + cq * 8;
        bSrc[t] = Bp + (size_t)row * D_DIM + cq * 8;
    }

    const int NCH = D_DIM / CH;   // 16
    auto issue = [&](int it, int s) {
        int k0 = it * CH;
        u32 base = tb + s * STG_BYTES;
#pragma unroll
        for (int t = 0; t < 8; t++)
            cp16(base + dOff[t], aSrc[t] + k0);
#pragma unroll
        for (int t = 0; t < 8; t++)
            cp16(base + 16384 + dOff[t], bSrc[t] + k0);
        cp_commit();
    };
    issue(0, 0); issue(1, 1);

    float acc[4][8][4];
#pragma unroll
    for (int i = 0; i < 4; i++)
#pragma unroll
        for (int j = 0; j < 8; j++)
#pragma unroll
            for (int k = 0; k < 4; k++) acc[i][j][k] = 0.f;

    for (int it = 0; it < NCH; ++it) {
        asm volatile("cp.async.wait_group 1;" ::: "memory");
        __syncthreads();
        if (it + 2 < NCH) issue(it + 2, (it + 2) % STAGES);
        gemm_inner(acc, tb + (it % STAGES) * STG_BYTES, wm, wn, lane);
    }

    // epilogue: bias + fast gelu -> fp16
#pragma unroll
    for (int mf = 0; mf < 4; ++mf) {
        int rb = row0 + wm * 64 + mf * 16 + (lane >> 2);
#pragma unroll
        for (int half = 0; half < 2; ++half) {
            int r = rb + half * 8;
            if (r < cnt) {
                size_t rowoff = ((size_t)e * T_TOK + r) * H_DIM;
#pragma unroll
                for (int nf = 0; nf < 8; ++nf) {
                    int cl = wn * 64 + nf * 8 + (lane & 3) * 2;
                    float v0 = gelu_fast(acc[mf][nf][half * 2 + 0] + sBias[cl]);
                    float v1 = gelu_fast(acc[mf][nf][half * 2 + 1] + sBias[cl + 1]);
                    *reinterpret_cast<u32*>(g_h + rowoff + n0 + cl) =
                        pack_h2(__float2half_rn(v0), __float2half_rn(v1));
                }
            }
        }
    }
}

// ---------------------------------------------------------------------------
// GEMM2: h @ W2 -> g_y (fp16, plain stores)
// ---------------------------------------------------------------------------
__global__ __launch_bounds__(128, 2) void gemm2_mma(const float* __restrict__ b2)
{
    int e    = blockIdx.z;
    int cnt  = g_cnt[e];
    int row0 = blockIdx.y * 128;
    if (row0 >= cnt) return;
    int n0 = blockIdx.x * 128;

    extern __shared__ char smem[];
    float* sBias = (float*)smem;
    u32 tb = cvta_smem(smem + 2048);

    int tid = threadIdx.x, lane = tid & 31, wid = tid >> 5;
    int wm = wid & 1, wn = wid >> 1;

    sBias[tid] = b2[e * D_DIM + n0 + tid];
    __syncthreads();

    const __half* Ap = g_h + (size_t)e * T_TOK * H_DIM;
    const __half* Bp = g_w2 + ((size_t)e * D_DIM + n0) * H_DIM;

    int rbase = tid >> 3, cq = tid & 7;
    u32 dOff[8];
    const __half* aSrc[8];
    const __half* bSrc[8];
#pragma unroll
    for (int t = 0; t < 8; t++) {
        int row = t * 16 + rbase;
        dOff[t] = swz128((row << 7) + (cq << 4));
        int rr = row0 + row;
        if (rr >= cnt) rr = cnt - 1;
        aSrc[t] = Ap + (size_t)rr * H_DIM + cq * 8;
        bSrc[t] = Bp + (size_t)row * H_DIM + cq * 8;
    }

    const int NCH = H_DIM / CH;   // 32
    auto issue = [&](int it, int s) {
        int k0 = it * CH;
        u32 base = tb + s * STG_BYTES;
#pragma unroll
        for (int t = 0; t < 8; t++)
            cp16(base + dOff[t], aSrc[t] + k0);
#pragma unroll
        for (int t = 0; t < 8; t++)
            cp16(base + 16384 + dOff[t], bSrc[t] + k0);
        cp_commit();
    };
    issue(0, 0); issue(1, 1);

    float acc[4][8][4];
#pragma unroll
    for (int i = 0; i < 4; i++)
#pragma unroll
        for (int j = 0; j < 8; j++)
#pragma unroll
            for (int k = 0; k < 4; k++) acc[i][j][k] = 0.f;

    for (int it = 0; it < NCH; ++it) {
        asm volatile("cp.async.wait_group 1;" ::: "memory");
        __syncthreads();
        if (it + 2 < NCH) issue(it + 2, (it + 2) % STAGES);
        gemm_inner(acc, tb + (it % STAGES) * STG_BYTES, wm, wn, lane);
    }

    // epilogue: g_y = fp16(y + b2)
#pragma unroll
    for (int mf = 0; mf < 4; ++mf) {
        int rb = row0 + wm * 64 + mf * 16 + (lane >> 2);
#pragma unroll
        for (int half = 0; half < 2; ++half) {
            int r = rb + half * 8;
            if (r < cnt) {
                __half* yrow = g_y + ((size_t)e * T_TOK + r) * D_DIM + n0;
#pragma unroll
                for (int nf = 0; nf < 8; ++nf) {
                    int cl = wn * 64 + nf * 8 + (lane & 3) * 2;
                    float v0 = acc[mf][nf][half * 2 + 0] + sBias[cl];
                    float v1 = acc[mf][nf][half * 2 + 1] + sBias[cl + 1];
                    *reinterpret_cast<u32*>(yrow + cl) =
                        pack_h2(__float2half_rn(v0), __float2half_rn(v1));
                }
            }
        }
    }
}

// ---------------------------------------------------------------------------
// combine: out[t] = w0*y[slot0] + w1*y[slot1] (fp16 sources); + aux loss
// ---------------------------------------------------------------------------
__global__ __launch_bounds__(512) void combine_kernel(float* __restrict__ out,
                                                      int do_aux)
{
    size_t i = (size_t)blockIdx.x * blockDim.x + threadIdx.x;   // T*D/4
    int t = (int)(i >> 8);
    int d4 = (int)(i & 255);
    int2   sl = g_slot[t];
    float2 w  = g_tw[t];
    uint2 p0 = reinterpret_cast<const uint2*>(g_y)[(size_t)sl.x * 256 + d4];
    uint2 p1 = reinterpret_cast<const uint2*>(g_y)[(size_t)sl.y * 256 + d4];
    float2 a0 = __half22float2(*reinterpret_cast<__half2*>(&p0.x));
    float2 a1 = __half22float2(*reinterpret_cast<__half2*>(&p0.y));
    float2 b0 = __half22float2(*reinterpret_cast<__half2*>(&p1.x));
    float2 b1 = __half22float2(*reinterpret_cast<__half2*>(&p1.y));
    float4 o;
    o.x = w.x * a0.x + w.y * b0.x;
    o.y = w.x * a0.y + w.y * b0.y;
    o.z = w.x * a1.x + w.y * b1.x;
    o.w = w.x * a1.y + w.y * b1.y;
    reinterpret_cast<float4*>(out)[i] = o;

    if (do_aux && blockIdx.x == 0 && threadIdx.x == 0) {
        int tot = 0;
#pragma unroll
        for (int e = 0; e < NE; e++) tot += g_cnt[e];
        float denom = fmaxf((float)tot, 1.f);
        float s = 0.f;
#pragma unroll
        for (int e = 0; e < NE; e++)
            s += (g_imp[e] / (float)T_TOK) * ((float)g_cnt[e] / denom);
        out[(size_t)T_TOK * D_DIM] = (float)NE * s;
    }
}

// ---------------------------------------------------------------------------
extern "C" void kernel_launch(void* const* d_in, const int* in_sizes, int n_in,
                              void* d_out, int out_size)
{
    const float* x  = (const float*)d_in[0];
    const float* Wr = (const float*)d_in[1];
    const float* br = (const float*)d_in[2];
    const float* W1 = (const float*)d_in[3];
    const float* b1 = (const float*)d_in[4];
    const float* W2 = (const float*)d_in[5];
    const float* b2 = (const float*)d_in[6];
    float* out = (float*)d_out;

    cudaFuncSetAttribute(gemm1_mma, cudaFuncAttributeMaxDynamicSharedMemorySize, SMEM_BYTES);
    cudaFuncSetAttribute(gemm2_mma, cudaFuncAttributeMaxDynamicSharedMemorySize, SMEM_BYTES);

    int do_aux = (out_size > T_TOK * D_DIM) ? 1 : 0;

    prep_kernel<<<T_TOK * D_DIM / 4 / 512, 512>>>(x);
    router_kernel<<<T_TOK / 8, 256>>>(x, Wr, br);
    convT2_kernel<<<32768, 256>>>(W1, W2);
    gemm1_mma<<<dim3(H_DIM / 128, T_TOK / 128, NE), 128, SMEM_BYTES>>>(b1);
    gemm2_mma<<<dim3(D_DIM / 128, T_TOK / 128, NE), 128, SMEM_BYTES>>>(b2);
    combine_kernel<<<T_TOK * D_DIM / 4 / 512, 512>>>(out, do_aux);
}